// round 10
// baseline (speedup 1.0000x reference)
#include <cuda_runtime.h>
#include <cuda_fp16.h>
#include <cstdint>
#include <cstddef>

// ---------------------------------------------------------------------------
// FastKAN as ONE 2:4-SPARSE fp16 GEMM (mma.sp::ordered_metadata.m16n8k32).
// Logical K' = 40 slots per i (padded for 2:4 legality):
//   pos 0..17  : even coeffs c=2p   | pos 20..36 : odd coeffs c=2p+1
//   pos 37     : silu slot          | pos 18,19,38,39 : zero pad
// A stored compressed (20 halves per i) + 2-bit/elem ordered metadata.
// Round 10: kan_gemm -> 512 threads, 4(M)x4(N) warps, warp tile 64x32.
// acc 128->64 regs (no spill), 4 warps/SMSP for latency hiding. Preps frozen.
// ---------------------------------------------------------------------------

#define BATCH   4096
#define INDIM   1024
#define OUTDIM  1024
#define NC      35
#define SLOTSP  40
#define KTOTL   (INDIM * SLOTSP)     // 40960 logical K
#define KTOTC   (KTOTL / 2)          // 20480 compressed halves per b
#define NMW     (KTOTL / 16)         // 2560 metadata u16 words per b

#define BM      256
#define BN      128
#define ITERS   (KTOTL / 128)        // 320
#define A_ST    32768                // 256 rows x 128 B (compressed A)
#define B_ST    16384                // 128 rows x 128 B (one k-half of B)
#define M_ST    4096                 // 128 pairs x 32 B metadata
#define STGB    (A_ST + 2 * B_ST + M_ST)   // 69632
#define SMEM_TOTAL (3 * STGB)              // 208896

__device__ __align__(128) __half g_Ac[(size_t)BATCH * KTOTC];        // 168 MB
__device__ __align__(128) __half g_B [(size_t)OUTDIM * KTOTL];       //  80 MB
__device__ __align__(128) unsigned short g_Mp[(size_t)BATCH * NMW];  //  20 MB
// g_Mp paired layout: u16 at ((pair*NMW + w)*2 + hb), pair=(b>>4)*8+(b&7),
// hb=(b>>3)&1  ->  u32 word (pair*NMW + w) = {row b (lo16), row b+8 (hi16)}.

// ------------------------------- helpers -----------------------------------
__device__ __forceinline__ uint32_t smem_u32(const void* p) {
    uint32_t a;
    asm("{ .reg .u64 t; cvta.to.shared.u64 t, %1; cvt.u32.u64 %0, t; }" : "=r"(a) : "l"(p));
    return a;
}
__device__ __forceinline__ void cp16(uint32_t s, const void* g) {
    asm volatile("cp.async.cg.shared.global [%0], [%1], 16;" :: "r"(s), "l"(g) : "memory");
}
#define CP_COMMIT() asm volatile("cp.async.commit_group;" ::: "memory")
#define CP_WAIT(n)  asm volatile("cp.async.wait_group %0;" :: "n"(n) : "memory")
#define SWZ(off) ((off) ^ (((off) >> 3) & 0x70))

__device__ __forceinline__ float tapval(float xn, const float* grid, int c) {
    float d = fabsf(xn - __ldg(grid + c)) * 17.0f;
    float inner = 0.66666667f - d * d + d * d * d * 0.5f;
    float tt = 2.0f - d;
    float outer = tt * tt * tt * (1.0f / 6.0f);
    return (d < 1.0f) ? inner : ((d < 2.0f) ? outer : 0.0f);
}

// ---------------------------------------------------------------------------
// prep_B: pack W + base_scale into g_B[j][i*40+s] fp16.
// One thread = one kk PAIR (half2 store) x 8 j's -> MLP 16, 4-B stores.
// ---------------------------------------------------------------------------
__global__ void prep_B(const float* __restrict__ W, const float* __restrict__ bs) {
    int t  = blockIdx.x * 256 + threadIdx.x;    // [0, 20480) pair index
    int kk = 2 * t;
    int i  = kk / SLOTSP;
    int s0 = kk - i * SLOTSP;                   // even
    int s1 = s0 + 1;                            // same i (SLOTSP even)
    int j0 = blockIdx.y * 8;

    int c0 = -1, c1 = -1;
    if (s0 < 18)                   c0 = 2 * s0;
    else if (s0 >= 20 && s0 <= 36) c0 = 2 * (s0 - 20) + 1;
    else if (s0 == 37)             c0 = -2;
    if (s1 < 18)                   c1 = 2 * s1;
    else if (s1 >= 20 && s1 <= 36) c1 = 2 * (s1 - 20) + 1;
    else if (s1 == 37)             c1 = -2;

    #pragma unroll
    for (int q = 0; q < 8; q++) {
        int j = j0 + q;
        const float* wr = W + ((size_t)i * OUTDIM + j) * NC;
        float v0 = 0.f, v1 = 0.f;
        if (c0 >= 0)       v0 = wr[c0];
        else if (c0 == -2) v0 = bs[(size_t)i * OUTDIM + j];
        if (c1 >= 0)       v1 = wr[c1];
        else if (c1 == -2) v1 = bs[(size_t)i * OUTDIM + j];
        *(half2*)(g_B + (size_t)j * KTOTL + kk) = __floats2half2_rn(v0, v1);
    }
}

// ---------------------------------------------------------------------------
// prep_A: compressed A (2 stored per 4-group) + ordered 2-bit metadata.
// One thread handles 2 i's (metadata lands on u16 boundaries: 5 u16).
// ---------------------------------------------------------------------------
__global__ void prep_A(const float* __restrict__ x, const float* __restrict__ grid) {
    __shared__ __half sbuf[256 * 40];
    int tid  = threadIdx.x;
    int b    = blockIdx.x >> 1;
    int half = blockIdx.x & 1;

    unsigned long long mbits[2];
    #pragma unroll
    for (int w = 0; w < 2; w++) {
        int i = half * 512 + 2 * tid + w;
        float xv = x[(size_t)b * INDIM + i];
        float xn = fminf(fmaxf(xv, -0.99f), 0.99f);
        float t  = (xn + 1.0f) * 17.0f;
        int cl = (int)floorf(t) - 1;
        int a  = cl > 0 ? cl : 0;
        int ub = cl + 3 < 34 ? cl + 3 : 34;
        int ce0 = a + (a & 1);
        int ce1 = ce0 + 2;
        int o0  = a + 1 - (a & 1);
        int o1  = o0 + 2;
        bool ho1 = (o1 <= ub);

        int   cp[5]; float cv[5]; bool cok[5];
        cp[0] = ce0 >> 1;             cv[0] = tapval(xn, grid, ce0);           cok[0] = true;
        cp[1] = ce1 >> 1;             cv[1] = tapval(xn, grid, ce1);           cok[1] = true;
        cp[2] = 20 + ((o0 - 1) >> 1); cv[2] = tapval(xn, grid, o0);            cok[2] = true;
        cp[3] = 20 + ((o1 - 1) >> 1); cv[3] = tapval(xn, grid, ho1 ? o1 : 34); cok[3] = ho1;
        cp[4] = 37;                   cv[4] = xn / (1.0f + __expf(-xn));       cok[4] = true;

        unsigned long long m = 0;
        #pragma unroll
        for (int u = 0; u < 10; u++) {
            int e0 = -1, e1 = -1; float v0 = 0.f, v1 = 0.f;
            #pragma unroll
            for (int q = 0; q < 5; q++) {
                if (cok[q] && (cp[q] >> 2) == u) {
                    if (e0 < 0) { e0 = cp[q] & 3; v0 = cv[q]; }
                    else        { e1 = cp[q] & 3; v1 = cv[q]; }
                }
            }
            if (e0 < 0) { e0 = 0; e1 = 1; }
            else if (e1 < 0) {
                if (e0 == 3) { e1 = 3; v1 = v0; e0 = 2; v0 = 0.f; }
                else         { e1 = 3; }
            }
            sbuf[tid * 40 + w * 20 + 2 * u]     = __float2half_rn(v0);
            sbuf[tid * 40 + w * 20 + 2 * u + 1] = __float2half_rn(v1);
            m |= (unsigned long long)(e0 | (e1 << 2)) << (4 * u);
        }
        mbits[w] = m;
    }

    {   // pack 2x40 metadata bits into 5 u16, store into paired layout
        unsigned long long m0 = mbits[0], m1 = mbits[1];
        unsigned short ws[5];
        ws[0] = (unsigned short)(m0);
        ws[1] = (unsigned short)(m0 >> 16);
        ws[2] = (unsigned short)(((m0 >> 32) & 0xFFull) | ((m1 & 0xFFull) << 8));
        ws[3] = (unsigned short)(m1 >> 8);
        ws[4] = (unsigned short)(m1 >> 24);
        int pairidx = (b >> 4) * 8 + (b & 7);
        int hb = (b >> 3) & 1;
        unsigned short* mp = g_Mp + ((size_t)pairidx * NMW + half * 1280 + 5 * tid) * 2 + hb;
        #pragma unroll
        for (int q = 0; q < 5; q++) mp[2 * q] = ws[q];
    }

    __syncthreads();
    const uint32_t* s4 = (const uint32_t*)sbuf;
    uint32_t* g4 = (uint32_t*)(g_Ac + ((size_t)b * KTOTC + half * 10240));
    #pragma unroll
    for (int q = 0; q < 20; q++) g4[q * 256 + tid] = s4[q * 256 + tid];
}

// ---------------------------------------------------------------------------
// kan_gemm: 256x128 tile, 3-stage cp.async + mma.sp::ordered_metadata
// m16n8k32. 512 threads, 16 warps as 4(M)x4(N), warp tile 64x32.
// 128 CTAs = one wave. acc=64 regs/thread, 4 warps/SMSP.
// ---------------------------------------------------------------------------
__global__ void __launch_bounds__(512, 1) kan_gemm(float* __restrict__ out) {
    extern __shared__ __align__(1024) char smem[];
    uint32_t sb0 = smem_u32(smem);
    int tid = threadIdx.x;
    int wid = tid >> 5;
    int lid = tid & 31;
    int tn  = blockIdx.x;       // [0,8)
    int tm  = blockIdx.y;       // [0,16)
    int wm  = wid & 3;          // 4 warps along M
    int wn  = wid >> 2;         // 4 warps along N

    const __half* gA = g_Ac + (size_t)(tm * BM) * KTOTC;
    const __half* gB = g_B + (size_t)(tn * BN) * KTOTL;
    const uint32_t* gM = ((const uint32_t*)g_Mp) + (size_t)(tm * 128) * NMW;

    // copy coords (512 threads): A 4 chunks, B 2 per half, meta tid<256
    uint32_t aoff[4], adst[4];
    #pragma unroll
    for (int q = 0; q < 4; q++) {
        int ci = tid + q * 512;
        int row = ci >> 3, c8 = ci & 7;
        aoff[q] = (uint32_t)row * KTOTC + c8 * 8;
        adst[q] = SWZ((uint32_t)row * 128 + c8 * 16);
    }
    uint32_t boff[2], bdst[2];
    #pragma unroll
    for (int q = 0; q < 2; q++) {
        int ci = tid + q * 512;
        int row = ci >> 3, c8 = ci & 7;
        boff[q] = (uint32_t)row * KTOTL + c8 * 8;
        bdst[q] = SWZ((uint32_t)row * 128 + c8 * 16);
    }
    int mpp = tid >> 1;                 // valid for tid < 256
    int mhh = tid & 1;
    uint32_t moff = (uint32_t)mpp * NMW + mhh * 4;
    uint32_t mdst = (uint32_t)mpp * 32 + (uint32_t)((mhh ^ ((mpp >> 2) & 1)) * 16);
    bool domem = (tid < 256);

    uint32_t afb = (uint32_t)(wm * 64 + (lid & 15)) * 128 + (lid >> 4) * 16;
    uint32_t bfb = (uint32_t)(wn * 32 + (lid & 7)) * 128 + (lid >> 3) * 16;
    int qg = lid >> 2;
    int c2 = lid & 1;

    float acc[4][4][4];
    #pragma unroll
    for (int a = 0; a < 4; a++)
        #pragma unroll
        for (int b = 0; b < 4; b++)
            #pragma unroll
            for (int c = 0; c < 4; c++) acc[a][b][c] = 0.f;

    auto copy_stage = [&](int it) {
        int s = it % 3;
        uint32_t sa  = sb0 + s * STGB;
        uint32_t sB0 = sa + A_ST, sB1 = sB0 + B_ST, sM = sB1 + B_ST;
        uint32_t k64 = (uint32_t)it * 64;
        uint32_t kL  = (uint32_t)it * 128;
        #pragma unroll
        for (int q = 0; q < 4; q++)
            cp16(sa + adst[q], gA + aoff[q] + k64);
        #pragma unroll
        for (int q = 0; q < 2; q++)
            cp16(sB0 + bdst[q], gB + boff[q] + kL);
        #pragma unroll
        for (int q = 0; q < 2; q++)
            cp16(sB1 + bdst[q], gB + boff[q] + kL + 64);
        if (domem)
            cp16(sM + mdst, (const char*)(gM + moff + (uint32_t)it * 8));
        CP_COMMIT();
    };

    copy_stage(0); copy_stage(1);

    for (int k = 0; k < ITERS; k++) {
        CP_WAIT(1);
        __syncthreads();
        if (k + 2 < ITERS) copy_stage(k + 2); else CP_COMMIT();

        int s = k % 3;
        uint32_t sa  = sb0 + s * STGB;
        uint32_t sB0 = sa + A_ST, sB1 = sB0 + B_ST, sM = sB1 + B_ST;

        #pragma unroll
        for (int ks = 0; ks < 4; ks++) {
            uint32_t af[4][4];
            uint32_t em[4];
            #pragma unroll
            for (int mt = 0; mt < 4; mt++) {
                uint32_t addr = sa + SWZ(afb + mt * 2048 + ks * 32);
                asm volatile(
                    "ldmatrix.sync.aligned.m8n8.x4.shared.b16 {%0,%1,%2,%3}, [%4];"
                    : "=r"(af[mt][0]), "=r"(af[mt][1]), "=r"(af[mt][2]), "=r"(af[mt][3])
                    : "r"(addr));
            }
            #pragma unroll
            for (int mt = 0; mt < 4; mt++) {
                uint32_t pr = (uint32_t)((wm * 4 + mt) * 8 + qg);
                uint32_t ma = sM + pr * 32 + ((uint32_t)((ks * 2 + c2) * 4) ^ ((pr & 4) << 2));
                asm volatile("ld.shared.b32 %0, [%1];" : "=r"(em[mt]) : "r"(ma));
            }
            uint32_t bh = (ks < 2) ? sB0 : sB1;
            uint32_t kb = (uint32_t)(ks & 1) * 64;
            uint32_t bf[4][4];
            #pragma unroll
            for (int j = 0; j < 4; j++) {
                uint32_t addr = bh + SWZ(bfb + j * 1024 + kb);
                asm volatile(
                    "ldmatrix.sync.aligned.m8n8.x4.shared.b16 {%0,%1,%2,%3}, [%4];"
                    : "=r"(bf[j][0]), "=r"(bf[j][1]), "=r"(bf[j][2]), "=r"(bf[j][3])
                    : "r"(addr));
            }
            #pragma unroll
            for (int mt = 0; mt < 4; mt++)
                #pragma unroll
                for (int j = 0; j < 4; j++) {
                    asm volatile(
                        "mma.sp::ordered_metadata.sync.aligned.m16n8k32.row.col.f32.f16.f16.f32 "
                        "{%0,%1,%2,%3}, {%4,%5,%6,%7}, {%8,%9,%10,%11}, {%0,%1,%2,%3}, %12, 0x0;"
                        : "+f"(acc[mt][j][0]), "+f"(acc[mt][j][1]),
                          "+f"(acc[mt][j][2]), "+f"(acc[mt][j][3])
                        : "r"(af[mt][0]), "r"(af[mt][1]), "r"(af[mt][2]), "r"(af[mt][3]),
                          "r"(bf[j][0]), "r"(bf[j][1]), "r"(bf[j][2]), "r"(bf[j][3]),
                          "r"(em[mt]));
                }
        }
    }
    CP_WAIT(0);

    #pragma unroll
    for (int mt = 0; mt < 4; mt++) {
        int r0 = tm * BM + wm * 64 + mt * 16 + (lid >> 2);
        #pragma unroll
        for (int nt = 0; nt < 4; nt++) {
            int c0 = tn * BN + wn * 32 + nt * 8 + (lid & 3) * 2;
            *(float2*)(out + (size_t)r0 * OUTDIM + c0) =
                make_float2(acc[mt][nt][0], acc[mt][nt][1]);
            *(float2*)(out + (size_t)(r0 + 8) * OUTDIM + c0) =
                make_float2(acc[mt][nt][2], acc[mt][nt][3]);
        }
    }
}

// ---------------------------------------------------------------------------
extern "C" void kernel_launch(void* const* d_in, const int* in_sizes, int n_in,
                              void* d_out, int out_size) {
    const float* x    = (const float*)d_in[0];
    const float* W    = (const float*)d_in[1];
    const float* bs   = (const float*)d_in[2];
    const float* grid = (const float*)d_in[3];
    float* out = (float*)d_out;

    cudaFuncSetAttribute(kan_gemm, cudaFuncAttributeMaxDynamicSharedMemorySize, SMEM_TOTAL);

    prep_B<<<dim3(KTOTC / 256, OUTDIM / 8), 256>>>(W, bs);
    prep_A<<<BATCH * 2, 256>>>(x, grid);
    kan_gemm<<<dim3(OUTDIM / BN, BATCH / BM), 512, SMEM_TOTAL>>>(out);
}

// round 11
// speedup vs baseline: 1.0740x; 1.0740x over previous
#include <cuda_runtime.h>
#include <cuda_fp16.h>
#include <cstdint>
#include <cstddef>

// ---------------------------------------------------------------------------
// FastKAN as ONE 2:4-SPARSE fp16 GEMM (mma.sp::ordered_metadata.m16n8k32).
// Logical K' = 40 slots per i (padded for 2:4 legality):
//   pos 0..17  : even coeffs c=2p   | pos 20..36 : odd coeffs c=2p+1
//   pos 37     : silu slot          | pos 18,19,38,39 : zero pad
// A stored compressed (20 halves per i) + 2-bit/elem ordered metadata.
// Round 11: GEMM + preps frozen at R9 (best measured). New: prep_A and
// prep_B run CONCURRENTLY via fork/join streams (graph-capturable pattern).
// ---------------------------------------------------------------------------

#define BATCH   4096
#define INDIM   1024
#define OUTDIM  1024
#define NC      35
#define SLOTSP  40
#define KTOTL   (INDIM * SLOTSP)     // 40960 logical K
#define KTOTC   (KTOTL / 2)          // 20480 compressed halves per b
#define NMW     (KTOTL / 16)         // 2560 metadata u16 words per b

#define BM      256
#define BN      128
#define ITERS   (KTOTL / 128)        // 320
#define A_ST    32768                // 256 rows x 128 B (compressed A)
#define B_ST    16384                // 128 rows x 128 B (one k-half of B)
#define M_ST    4096                 // 128 pairs x 32 B metadata
#define STGB    (A_ST + 2 * B_ST + M_ST)   // 69632
#define SMEM_TOTAL (3 * STGB)              // 208896

__device__ __align__(128) __half g_Ac[(size_t)BATCH * KTOTC];        // 168 MB
__device__ __align__(128) __half g_B [(size_t)OUTDIM * KTOTL];       //  80 MB
__device__ __align__(128) unsigned short g_Mp[(size_t)BATCH * NMW];  //  20 MB
// g_Mp paired layout: u16 at ((pair*NMW + w)*2 + hb), pair=(b>>4)*8+(b&7),
// hb=(b>>3)&1  ->  u32 word (pair*NMW + w) = {row b (lo16), row b+8 (hi16)}.

// ------------------------------- helpers -----------------------------------
__device__ __forceinline__ uint32_t smem_u32(const void* p) {
    uint32_t a;
    asm("{ .reg .u64 t; cvta.to.shared.u64 t, %1; cvt.u32.u64 %0, t; }" : "=r"(a) : "l"(p));
    return a;
}
__device__ __forceinline__ void cp16(uint32_t s, const void* g) {
    asm volatile("cp.async.cg.shared.global [%0], [%1], 16;" :: "r"(s), "l"(g) : "memory");
}
#define CP_COMMIT() asm volatile("cp.async.commit_group;" ::: "memory")
#define CP_WAIT(n)  asm volatile("cp.async.wait_group %0;" :: "n"(n) : "memory")
#define SWZ(off) ((off) ^ (((off) >> 3) & 0x70))

__device__ __forceinline__ float tapval(float xn, const float* grid, int c) {
    float d = fabsf(xn - __ldg(grid + c)) * 17.0f;
    float inner = 0.66666667f - d * d + d * d * d * 0.5f;
    float tt = 2.0f - d;
    float outer = tt * tt * tt * (1.0f / 6.0f);
    return (d < 1.0f) ? inner : ((d < 2.0f) ? outer : 0.0f);
}

// ---------------------------------------------------------------------------
// prep_B: pack W + base_scale into g_B[j][i*40+s] fp16.
// One thread = one kk PAIR (half2 store) x 8 j's -> MLP 16, 4-B stores.
// ---------------------------------------------------------------------------
__global__ void prep_B(const float* __restrict__ W, const float* __restrict__ bs) {
    int t  = blockIdx.x * 256 + threadIdx.x;    // [0, 20480) pair index
    int kk = 2 * t;
    int i  = kk / SLOTSP;
    int s0 = kk - i * SLOTSP;                   // even
    int s1 = s0 + 1;                            // same i (SLOTSP even)
    int j0 = blockIdx.y * 8;

    int c0 = -1, c1 = -1;
    if (s0 < 18)                   c0 = 2 * s0;
    else if (s0 >= 20 && s0 <= 36) c0 = 2 * (s0 - 20) + 1;
    else if (s0 == 37)             c0 = -2;
    if (s1 < 18)                   c1 = 2 * s1;
    else if (s1 >= 20 && s1 <= 36) c1 = 2 * (s1 - 20) + 1;
    else if (s1 == 37)             c1 = -2;

    #pragma unroll
    for (int q = 0; q < 8; q++) {
        int j = j0 + q;
        const float* wr = W + ((size_t)i * OUTDIM + j) * NC;
        float v0 = 0.f, v1 = 0.f;
        if (c0 >= 0)       v0 = wr[c0];
        else if (c0 == -2) v0 = bs[(size_t)i * OUTDIM + j];
        if (c1 >= 0)       v1 = wr[c1];
        else if (c1 == -2) v1 = bs[(size_t)i * OUTDIM + j];
        *(half2*)(g_B + (size_t)j * KTOTL + kk) = __floats2half2_rn(v0, v1);
    }
}

// ---------------------------------------------------------------------------
// prep_A: compressed A (2 stored per 4-group) + ordered 2-bit metadata.
// One thread handles 2 i's (metadata lands on u16 boundaries: 5 u16).
// ---------------------------------------------------------------------------
__global__ void prep_A(const float* __restrict__ x, const float* __restrict__ grid) {
    __shared__ __half sbuf[256 * 40];
    int tid  = threadIdx.x;
    int b    = blockIdx.x >> 1;
    int half = blockIdx.x & 1;

    unsigned long long mbits[2];
    #pragma unroll
    for (int w = 0; w < 2; w++) {
        int i = half * 512 + 2 * tid + w;
        float xv = x[(size_t)b * INDIM + i];
        float xn = fminf(fmaxf(xv, -0.99f), 0.99f);
        float t  = (xn + 1.0f) * 17.0f;
        int cl = (int)floorf(t) - 1;
        int a  = cl > 0 ? cl : 0;
        int ub = cl + 3 < 34 ? cl + 3 : 34;
        int ce0 = a + (a & 1);
        int ce1 = ce0 + 2;
        int o0  = a + 1 - (a & 1);
        int o1  = o0 + 2;
        bool ho1 = (o1 <= ub);

        int   cp[5]; float cv[5]; bool cok[5];
        cp[0] = ce0 >> 1;             cv[0] = tapval(xn, grid, ce0);           cok[0] = true;
        cp[1] = ce1 >> 1;             cv[1] = tapval(xn, grid, ce1);           cok[1] = true;
        cp[2] = 20 + ((o0 - 1) >> 1); cv[2] = tapval(xn, grid, o0);            cok[2] = true;
        cp[3] = 20 + ((o1 - 1) >> 1); cv[3] = tapval(xn, grid, ho1 ? o1 : 34); cok[3] = ho1;
        cp[4] = 37;                   cv[4] = xn / (1.0f + __expf(-xn));       cok[4] = true;

        unsigned long long m = 0;
        #pragma unroll
        for (int u = 0; u < 10; u++) {
            int e0 = -1, e1 = -1; float v0 = 0.f, v1 = 0.f;
            #pragma unroll
            for (int q = 0; q < 5; q++) {
                if (cok[q] && (cp[q] >> 2) == u) {
                    if (e0 < 0) { e0 = cp[q] & 3; v0 = cv[q]; }
                    else        { e1 = cp[q] & 3; v1 = cv[q]; }
                }
            }
            if (e0 < 0) { e0 = 0; e1 = 1; }
            else if (e1 < 0) {
                if (e0 == 3) { e1 = 3; v1 = v0; e0 = 2; v0 = 0.f; }
                else         { e1 = 3; }
            }
            sbuf[tid * 40 + w * 20 + 2 * u]     = __float2half_rn(v0);
            sbuf[tid * 40 + w * 20 + 2 * u + 1] = __float2half_rn(v1);
            m |= (unsigned long long)(e0 | (e1 << 2)) << (4 * u);
        }
        mbits[w] = m;
    }

    {   // pack 2x40 metadata bits into 5 u16, store into paired layout
        unsigned long long m0 = mbits[0], m1 = mbits[1];
        unsigned short ws[5];
        ws[0] = (unsigned short)(m0);
        ws[1] = (unsigned short)(m0 >> 16);
        ws[2] = (unsigned short)(((m0 >> 32) & 0xFFull) | ((m1 & 0xFFull) << 8));
        ws[3] = (unsigned short)(m1 >> 8);
        ws[4] = (unsigned short)(m1 >> 24);
        int pairidx = (b >> 4) * 8 + (b & 7);
        int hb = (b >> 3) & 1;
        unsigned short* mp = g_Mp + ((size_t)pairidx * NMW + half * 1280 + 5 * tid) * 2 + hb;
        #pragma unroll
        for (int q = 0; q < 5; q++) mp[2 * q] = ws[q];
    }

    __syncthreads();
    const uint32_t* s4 = (const uint32_t*)sbuf;
    uint32_t* g4 = (uint32_t*)(g_Ac + ((size_t)b * KTOTC + half * 10240));
    #pragma unroll
    for (int q = 0; q < 20; q++) g4[q * 256 + tid] = s4[q * 256 + tid];
}

// ---------------------------------------------------------------------------
// kan_gemm: 256x128 tile, 3-stage cp.async + mma.sp::ordered_metadata
// m16n8k32. 8 warps 4(M)x2(N), warp tile 64x64. 128 CTAs = one wave.
// (Frozen: best measured config, R9.)
// ---------------------------------------------------------------------------
__global__ void __launch_bounds__(256, 1) kan_gemm(float* __restrict__ out) {
    extern __shared__ __align__(1024) char smem[];
    uint32_t sb0 = smem_u32(smem);
    int tid = threadIdx.x;
    int wid = tid >> 5;
    int lid = tid & 31;
    int tn  = blockIdx.x;       // [0,8)
    int tm  = blockIdx.y;       // [0,16)
    int wm  = wid & 3;
    int wn  = wid >> 2;

    const __half* gA = g_Ac + (size_t)(tm * BM) * KTOTC;
    const __half* gB = g_B + (size_t)(tn * BN) * KTOTL;
    const uint32_t* gM = ((const uint32_t*)g_Mp) + (size_t)(tm * 128) * NMW;

    uint32_t aoff[8], adst[8];
    #pragma unroll
    for (int q = 0; q < 8; q++) {
        int ci = tid + q * 256;
        int row = ci >> 3, c8 = ci & 7;
        aoff[q] = (uint32_t)row * KTOTC + c8 * 8;
        adst[q] = SWZ((uint32_t)row * 128 + c8 * 16);
    }
    uint32_t boff[4], bdst[4];
    #pragma unroll
    for (int q = 0; q < 4; q++) {
        int ci = tid + q * 256;
        int row = ci >> 3, c8 = ci & 7;
        boff[q] = (uint32_t)row * KTOTL + c8 * 8;
        bdst[q] = SWZ((uint32_t)row * 128 + c8 * 16);
    }
    int mpp = tid >> 1;
    int mhh = tid & 1;
    uint32_t moff = (uint32_t)mpp * NMW + mhh * 4;
    uint32_t mdst = (uint32_t)mpp * 32 + (uint32_t)((mhh ^ ((mpp >> 2) & 1)) * 16);

    uint32_t afb = (uint32_t)(wm * 64 + (lid & 15)) * 128 + (lid >> 4) * 16;
    uint32_t bfb = (uint32_t)(wn * 64 + (lid & 7)) * 128 + (lid >> 3) * 16;
    int qg = lid >> 2;
    int c2 = lid & 1;

    float acc[4][8][4];
    #pragma unroll
    for (int a = 0; a < 4; a++)
        #pragma unroll
        for (int b = 0; b < 8; b++)
            #pragma unroll
            for (int c = 0; c < 4; c++) acc[a][b][c] = 0.f;

    auto copy_stage = [&](int it) {
        int s = it % 3;
        uint32_t sa  = sb0 + s * STGB;
        uint32_t sB0 = sa + A_ST, sB1 = sB0 + B_ST, sM = sB1 + B_ST;
        uint32_t k64 = (uint32_t)it * 64;
        uint32_t kL  = (uint32_t)it * 128;
        #pragma unroll
        for (int q = 0; q < 8; q++)
            cp16(sa + adst[q], gA + aoff[q] + k64);
        #pragma unroll
        for (int q = 0; q < 4; q++)
            cp16(sB0 + bdst[q], gB + boff[q] + kL);
        #pragma unroll
        for (int q = 0; q < 4; q++)
            cp16(sB1 + bdst[q], gB + boff[q] + kL + 64);
        cp16(sM + mdst, (const char*)(gM + moff + (uint32_t)it * 8));
        CP_COMMIT();
    };

    copy_stage(0); copy_stage(1);

    for (int k = 0; k < ITERS; k++) {
        CP_WAIT(1);
        __syncthreads();
        if (k + 2 < ITERS) copy_stage(k + 2); else CP_COMMIT();

        int s = k % 3;
        uint32_t sa  = sb0 + s * STGB;
        uint32_t sB0 = sa + A_ST, sB1 = sB0 + B_ST, sM = sB1 + B_ST;

        #pragma unroll
        for (int ks = 0; ks < 4; ks++) {
            uint32_t af[4][4];
            uint32_t em[4];
            #pragma unroll
            for (int mt = 0; mt < 4; mt++) {
                uint32_t addr = sa + SWZ(afb + mt * 2048 + ks * 32);
                asm volatile(
                    "ldmatrix.sync.aligned.m8n8.x4.shared.b16 {%0,%1,%2,%3}, [%4];"
                    : "=r"(af[mt][0]), "=r"(af[mt][1]), "=r"(af[mt][2]), "=r"(af[mt][3])
                    : "r"(addr));
            }
            #pragma unroll
            for (int mt = 0; mt < 4; mt++) {
                uint32_t pr = (uint32_t)((wm * 4 + mt) * 8 + qg);
                uint32_t ma = sM + pr * 32 + ((uint32_t)((ks * 2 + c2) * 4) ^ ((pr & 4) << 2));
                asm volatile("ld.shared.b32 %0, [%1];" : "=r"(em[mt]) : "r"(ma));
            }
            uint32_t bh = (ks < 2) ? sB0 : sB1;
            uint32_t kb = (uint32_t)(ks & 1) * 64;
            #pragma unroll
            for (int nh = 0; nh < 2; nh++) {
                uint32_t bf[4][4];
                #pragma unroll
                for (int j = 0; j < 4; j++) {
                    int nt = nh * 4 + j;
                    uint32_t addr = bh + SWZ(bfb + nt * 1024 + kb);
                    asm volatile(
                        "ldmatrix.sync.aligned.m8n8.x4.shared.b16 {%0,%1,%2,%3}, [%4];"
                        : "=r"(bf[j][0]), "=r"(bf[j][1]), "=r"(bf[j][2]), "=r"(bf[j][3])
                        : "r"(addr));
                }
                #pragma unroll
                for (int mt = 0; mt < 4; mt++)
                    #pragma unroll
                    for (int j = 0; j < 4; j++) {
                        asm volatile(
                            "mma.sp::ordered_metadata.sync.aligned.m16n8k32.row.col.f32.f16.f16.f32 "
                            "{%0,%1,%2,%3}, {%4,%5,%6,%7}, {%8,%9,%10,%11}, {%0,%1,%2,%3}, %12, 0x0;"
                            : "+f"(acc[mt][nh * 4 + j][0]), "+f"(acc[mt][nh * 4 + j][1]),
                              "+f"(acc[mt][nh * 4 + j][2]), "+f"(acc[mt][nh * 4 + j][3])
                            : "r"(af[mt][0]), "r"(af[mt][1]), "r"(af[mt][2]), "r"(af[mt][3]),
                              "r"(bf[j][0]), "r"(bf[j][1]), "r"(bf[j][2]), "r"(bf[j][3]),
                              "r"(em[mt]));
                    }
            }
        }
    }
    CP_WAIT(0);

    #pragma unroll
    for (int mt = 0; mt < 4; mt++) {
        int r0 = tm * BM + wm * 64 + mt * 16 + (lid >> 2);
        #pragma unroll
        for (int nt = 0; nt < 8; nt++) {
            int c0 = tn * BN + wn * 64 + nt * 8 + (lid & 3) * 2;
            *(float2*)(out + (size_t)r0 * OUTDIM + c0) =
                make_float2(acc[mt][nt][0], acc[mt][nt][1]);
            *(float2*)(out + (size_t)(r0 + 8) * OUTDIM + c0) =
                make_float2(acc[mt][nt][2], acc[mt][nt][3]);
        }
    }
}

// ---------------------------------------------------------------------------
// Launch: prep_A (stream 0) runs CONCURRENTLY with prep_B (side stream),
// joined by event before kan_gemm. Standard capture-safe fork/join; stream
// and events are created lazily on the first (uncaptured) call only.
// ---------------------------------------------------------------------------
extern "C" void kernel_launch(void* const* d_in, const int* in_sizes, int n_in,
                              void* d_out, int out_size) {
    const float* x    = (const float*)d_in[0];
    const float* W    = (const float*)d_in[1];
    const float* bs   = (const float*)d_in[2];
    const float* grid = (const float*)d_in[3];
    float* out = (float*)d_out;

    static cudaStream_t s2 = nullptr;
    static cudaEvent_t evFork = nullptr, evJoin = nullptr;
    if (s2 == nullptr) {
        cudaStreamCreateWithFlags(&s2, cudaStreamNonBlocking);
        cudaEventCreateWithFlags(&evFork, cudaEventDisableTiming);
        cudaEventCreateWithFlags(&evJoin, cudaEventDisableTiming);
        cudaFuncSetAttribute(kan_gemm, cudaFuncAttributeMaxDynamicSharedMemorySize, SMEM_TOTAL);
    }

    // fork: side stream depends on everything prior on the main stream
    cudaEventRecord(evFork, 0);
    cudaStreamWaitEvent(s2, evFork, 0);

    prep_B<<<dim3(KTOTC / 256, OUTDIM / 8), 256, 0, s2>>>(W, bs);
    prep_A<<<BATCH * 2, 256>>>(x, grid);

    // join: main stream waits for prep_B before the GEMM
    cudaEventRecord(evJoin, s2);
    cudaStreamWaitEvent(0, evJoin, 0);

    kan_gemm<<<dim3(OUTDIM / BN, BATCH / BM), 256, SMEM_TOTAL>>>(out);
}

// round 12
// speedup vs baseline: 1.0900x; 1.0149x over previous
#include <cuda_runtime.h>
#include <cuda_fp16.h>
#include <cstdint>
#include <cstddef>

// ---------------------------------------------------------------------------
// FastKAN as ONE 2:4-SPARSE fp16 GEMM (mma.sp::ordered_metadata.m16n8k32).
// Logical K' = 40 slots per i (padded for 2:4 legality):
//   pos 0..17  : even coeffs c=2p   | pos 20..36 : odd coeffs c=2p+1
//   pos 37     : silu slot          | pos 18,19,38,39 : zero pad
// A stored compressed (20 halves per i) + 2-bit/elem ordered metadata.
// Round 12: serial launches (streams were neutral). GEMM: all 8 B-fragment
// LDSM hoisted to top of each ks block (latency hiding), mma loop j-outer;
// smem copy dsts recomputed per stage to free registers. Math unchanged.
// ---------------------------------------------------------------------------

#define BATCH   4096
#define INDIM   1024
#define OUTDIM  1024
#define NC      35
#define SLOTSP  40
#define KTOTL   (INDIM * SLOTSP)     // 40960 logical K
#define KTOTC   (KTOTL / 2)          // 20480 compressed halves per b
#define NMW     (KTOTL / 16)         // 2560 metadata u16 words per b

#define BM      256
#define BN      128
#define ITERS   (KTOTL / 128)        // 320
#define A_ST    32768                // 256 rows x 128 B (compressed A)
#define B_ST    16384                // 128 rows x 128 B (one k-half of B)
#define M_ST    4096                 // 128 pairs x 32 B metadata
#define STGB    (A_ST + 2 * B_ST + M_ST)   // 69632
#define SMEM_TOTAL (3 * STGB)              // 208896

__device__ __align__(128) __half g_Ac[(size_t)BATCH * KTOTC];        // 168 MB
__device__ __align__(128) __half g_B [(size_t)OUTDIM * KTOTL];       //  80 MB
__device__ __align__(128) unsigned short g_Mp[(size_t)BATCH * NMW];  //  20 MB
// g_Mp paired layout: u16 at ((pair*NMW + w)*2 + hb), pair=(b>>4)*8+(b&7),
// hb=(b>>3)&1  ->  u32 word (pair*NMW + w) = {row b (lo16), row b+8 (hi16)}.

// ------------------------------- helpers -----------------------------------
__device__ __forceinline__ uint32_t smem_u32(const void* p) {
    uint32_t a;
    asm("{ .reg .u64 t; cvta.to.shared.u64 t, %1; cvt.u32.u64 %0, t; }" : "=r"(a) : "l"(p));
    return a;
}
__device__ __forceinline__ void cp16(uint32_t s, const void* g) {
    asm volatile("cp.async.cg.shared.global [%0], [%1], 16;" :: "r"(s), "l"(g) : "memory");
}
#define CP_COMMIT() asm volatile("cp.async.commit_group;" ::: "memory")
#define CP_WAIT(n)  asm volatile("cp.async.wait_group %0;" :: "n"(n) : "memory")
#define SWZ(off) ((off) ^ (((off) >> 3) & 0x70))

__device__ __forceinline__ float tapval(float xn, const float* grid, int c) {
    float d = fabsf(xn - __ldg(grid + c)) * 17.0f;
    float inner = 0.66666667f - d * d + d * d * d * 0.5f;
    float tt = 2.0f - d;
    float outer = tt * tt * tt * (1.0f / 6.0f);
    return (d < 1.0f) ? inner : ((d < 2.0f) ? outer : 0.0f);
}

// ---------------------------------------------------------------------------
// prep_B: pack W + base_scale into g_B[j][i*40+s] fp16.
// One thread = one kk PAIR (half2 store) x 8 j's -> MLP 16, 4-B stores.
// ---------------------------------------------------------------------------
__global__ void prep_B(const float* __restrict__ W, const float* __restrict__ bs) {
    int t  = blockIdx.x * 256 + threadIdx.x;    // [0, 20480) pair index
    int kk = 2 * t;
    int i  = kk / SLOTSP;
    int s0 = kk - i * SLOTSP;                   // even
    int s1 = s0 + 1;                            // same i (SLOTSP even)
    int j0 = blockIdx.y * 8;

    int c0 = -1, c1 = -1;
    if (s0 < 18)                   c0 = 2 * s0;
    else if (s0 >= 20 && s0 <= 36) c0 = 2 * (s0 - 20) + 1;
    else if (s0 == 37)             c0 = -2;
    if (s1 < 18)                   c1 = 2 * s1;
    else if (s1 >= 20 && s1 <= 36) c1 = 2 * (s1 - 20) + 1;
    else if (s1 == 37)             c1 = -2;

    #pragma unroll
    for (int q = 0; q < 8; q++) {
        int j = j0 + q;
        const float* wr = W + ((size_t)i * OUTDIM + j) * NC;
        float v0 = 0.f, v1 = 0.f;
        if (c0 >= 0)       v0 = wr[c0];
        else if (c0 == -2) v0 = bs[(size_t)i * OUTDIM + j];
        if (c1 >= 0)       v1 = wr[c1];
        else if (c1 == -2) v1 = bs[(size_t)i * OUTDIM + j];
        *(half2*)(g_B + (size_t)j * KTOTL + kk) = __floats2half2_rn(v0, v1);
    }
}

// ---------------------------------------------------------------------------
// prep_A: compressed A (2 stored per 4-group) + ordered 2-bit metadata.
// One thread handles 2 i's (metadata lands on u16 boundaries: 5 u16).
// ---------------------------------------------------------------------------
__global__ void prep_A(const float* __restrict__ x, const float* __restrict__ grid) {
    __shared__ __half sbuf[256 * 40];
    int tid  = threadIdx.x;
    int b    = blockIdx.x >> 1;
    int half = blockIdx.x & 1;

    unsigned long long mbits[2];
    #pragma unroll
    for (int w = 0; w < 2; w++) {
        int i = half * 512 + 2 * tid + w;
        float xv = x[(size_t)b * INDIM + i];
        float xn = fminf(fmaxf(xv, -0.99f), 0.99f);
        float t  = (xn + 1.0f) * 17.0f;
        int cl = (int)floorf(t) - 1;
        int a  = cl > 0 ? cl : 0;
        int ub = cl + 3 < 34 ? cl + 3 : 34;
        int ce0 = a + (a & 1);
        int ce1 = ce0 + 2;
        int o0  = a + 1 - (a & 1);
        int o1  = o0 + 2;
        bool ho1 = (o1 <= ub);

        int   cp[5]; float cv[5]; bool cok[5];
        cp[0] = ce0 >> 1;             cv[0] = tapval(xn, grid, ce0);           cok[0] = true;
        cp[1] = ce1 >> 1;             cv[1] = tapval(xn, grid, ce1);           cok[1] = true;
        cp[2] = 20 + ((o0 - 1) >> 1); cv[2] = tapval(xn, grid, o0);            cok[2] = true;
        cp[3] = 20 + ((o1 - 1) >> 1); cv[3] = tapval(xn, grid, ho1 ? o1 : 34); cok[3] = ho1;
        cp[4] = 37;                   cv[4] = xn / (1.0f + __expf(-xn));       cok[4] = true;

        unsigned long long m = 0;
        #pragma unroll
        for (int u = 0; u < 10; u++) {
            int e0 = -1, e1 = -1; float v0 = 0.f, v1 = 0.f;
            #pragma unroll
            for (int q = 0; q < 5; q++) {
                if (cok[q] && (cp[q] >> 2) == u) {
                    if (e0 < 0) { e0 = cp[q] & 3; v0 = cv[q]; }
                    else        { e1 = cp[q] & 3; v1 = cv[q]; }
                }
            }
            if (e0 < 0) { e0 = 0; e1 = 1; }
            else if (e1 < 0) {
                if (e0 == 3) { e1 = 3; v1 = v0; e0 = 2; v0 = 0.f; }
                else         { e1 = 3; }
            }
            sbuf[tid * 40 + w * 20 + 2 * u]     = __float2half_rn(v0);
            sbuf[tid * 40 + w * 20 + 2 * u + 1] = __float2half_rn(v1);
            m |= (unsigned long long)(e0 | (e1 << 2)) << (4 * u);
        }
        mbits[w] = m;
    }

    {   // pack 2x40 metadata bits into 5 u16, store into paired layout
        unsigned long long m0 = mbits[0], m1 = mbits[1];
        unsigned short ws[5];
        ws[0] = (unsigned short)(m0);
        ws[1] = (unsigned short)(m0 >> 16);
        ws[2] = (unsigned short)(((m0 >> 32) & 0xFFull) | ((m1 & 0xFFull) << 8));
        ws[3] = (unsigned short)(m1 >> 8);
        ws[4] = (unsigned short)(m1 >> 24);
        int pairidx = (b >> 4) * 8 + (b & 7);
        int hb = (b >> 3) & 1;
        unsigned short* mp = g_Mp + ((size_t)pairidx * NMW + half * 1280 + 5 * tid) * 2 + hb;
        #pragma unroll
        for (int q = 0; q < 5; q++) mp[2 * q] = ws[q];
    }

    __syncthreads();
    const uint32_t* s4 = (const uint32_t*)sbuf;
    uint32_t* g4 = (uint32_t*)(g_Ac + ((size_t)b * KTOTC + half * 10240));
    #pragma unroll
    for (int q = 0; q < 20; q++) g4[q * 256 + tid] = s4[q * 256 + tid];
}

// ---------------------------------------------------------------------------
// kan_gemm: 256x128 tile, 3-stage cp.async + mma.sp::ordered_metadata
// m16n8k32. 8 warps 4(M)x2(N), warp tile 64x64. 128 CTAs = one wave.
// R12: per-ks all-fragments-first (12 LDSM + 4 LDS), then 32 mma j-outer.
// ---------------------------------------------------------------------------
__global__ void __launch_bounds__(256, 1) kan_gemm(float* __restrict__ out) {
    extern __shared__ __align__(1024) char smem[];
    uint32_t sb0 = smem_u32(smem);
    int tid = threadIdx.x;
    int wid = tid >> 5;
    int lid = tid & 31;
    int tn  = blockIdx.x;       // [0,8)
    int tm  = blockIdx.y;       // [0,16)
    int wm  = wid & 3;
    int wn  = wid >> 2;

    const __half* gA = g_Ac + (size_t)(tm * BM) * KTOTC;
    const __half* gB = g_B + (size_t)(tn * BN) * KTOTL;
    const uint32_t* gM = ((const uint32_t*)g_Mp) + (size_t)(tm * 128) * NMW;

    // gmem element offsets only; swizzled smem dsts recomputed per stage
    uint32_t aoff[8];
    #pragma unroll
    for (int q = 0; q < 8; q++) {
        int ci = tid + q * 256;
        aoff[q] = (uint32_t)(ci >> 3) * KTOTC + (ci & 7) * 8;
    }
    uint32_t boff[4];
    #pragma unroll
    for (int q = 0; q < 4; q++) {
        int ci = tid + q * 256;
        boff[q] = (uint32_t)(ci >> 3) * KTOTL + (ci & 7) * 8;
    }
    int mpp = tid >> 1;
    int mhh = tid & 1;
    uint32_t moff = (uint32_t)mpp * NMW + mhh * 4;
    uint32_t mdst = (uint32_t)mpp * 32 + (uint32_t)((mhh ^ ((mpp >> 2) & 1)) * 16);

    uint32_t afb = (uint32_t)(wm * 64 + (lid & 15)) * 128 + (lid >> 4) * 16;
    uint32_t bfb = (uint32_t)(wn * 64 + (lid & 7)) * 128 + (lid >> 3) * 16;
    int qg = lid >> 2;
    int c2 = lid & 1;

    float acc[4][8][4];
    #pragma unroll
    for (int a = 0; a < 4; a++)
        #pragma unroll
        for (int b = 0; b < 8; b++)
            #pragma unroll
            for (int c = 0; c < 4; c++) acc[a][b][c] = 0.f;

    auto copy_stage = [&](int it) {
        int s = it % 3;
        uint32_t sa  = sb0 + s * STGB;
        uint32_t sB0 = sa + A_ST, sB1 = sB0 + B_ST, sM = sB1 + B_ST;
        uint32_t k64 = (uint32_t)it * 64;
        uint32_t kL  = (uint32_t)it * 128;
        #pragma unroll
        for (int q = 0; q < 8; q++) {
            int ci = tid + q * 256;
            uint32_t dst = SWZ((uint32_t)(ci >> 3) * 128 + (ci & 7) * 16);
            cp16(sa + dst, gA + aoff[q] + k64);
        }
        #pragma unroll
        for (int q = 0; q < 4; q++) {
            int ci = tid + q * 256;
            uint32_t dst = SWZ((uint32_t)(ci >> 3) * 128 + (ci & 7) * 16);
            cp16(sB0 + dst, gB + boff[q] + kL);
            cp16(sB1 + dst, gB + boff[q] + kL + 64);
        }
        cp16(sM + mdst, (const char*)(gM + moff + (uint32_t)it * 8));
        CP_COMMIT();
    };

    copy_stage(0); copy_stage(1);

    for (int k = 0; k < ITERS; k++) {
        CP_WAIT(1);
        __syncthreads();
        if (k + 2 < ITERS) copy_stage(k + 2); else CP_COMMIT();

        int s = k % 3;
        uint32_t sa  = sb0 + s * STGB;
        uint32_t sB0 = sa + A_ST, sB1 = sB0 + B_ST, sM = sB1 + B_ST;

        #pragma unroll
        for (int ks = 0; ks < 4; ks++) {
            uint32_t em[4];
            uint32_t af[4][4];
            uint32_t bf[8][4];
            // metadata first (LDS, consumed by every mma)
            #pragma unroll
            for (int mt = 0; mt < 4; mt++) {
                uint32_t pr = (uint32_t)((wm * 4 + mt) * 8 + qg);
                uint32_t ma = sM + pr * 32 + ((uint32_t)((ks * 2 + c2) * 4) ^ ((pr & 4) << 2));
                asm volatile("ld.shared.b32 %0, [%1];" : "=r"(em[mt]) : "r"(ma));
            }
            // A fragments
            #pragma unroll
            for (int mt = 0; mt < 4; mt++) {
                uint32_t addr = sa + SWZ(afb + mt * 2048 + ks * 32);
                asm volatile(
                    "ldmatrix.sync.aligned.m8n8.x4.shared.b16 {%0,%1,%2,%3}, [%4];"
                    : "=r"(af[mt][0]), "=r"(af[mt][1]), "=r"(af[mt][2]), "=r"(af[mt][3])
                    : "r"(addr));
            }
            // ALL 8 B fragments up front (latency hidden under mma stream)
            uint32_t bh = (ks < 2) ? sB0 : sB1;
            uint32_t kb = (uint32_t)(ks & 1) * 64;
            #pragma unroll
            for (int j = 0; j < 8; j++) {
                uint32_t addr = bh + SWZ(bfb + j * 1024 + kb);
                asm volatile(
                    "ldmatrix.sync.aligned.m8n8.x4.shared.b16 {%0,%1,%2,%3}, [%4];"
                    : "=r"(bf[j][0]), "=r"(bf[j][1]), "=r"(bf[j][2]), "=r"(bf[j][3])
                    : "r"(addr));
            }
            // 32 mma, j outer: bf[j] first consumed at mma #4j -> max slack
            #pragma unroll
            for (int j = 0; j < 8; j++)
                #pragma unroll
                for (int mt = 0; mt < 4; mt++) {
                    asm volatile(
                        "mma.sp::ordered_metadata.sync.aligned.m16n8k32.row.col.f32.f16.f16.f32 "
                        "{%0,%1,%2,%3}, {%4,%5,%6,%7}, {%8,%9,%10,%11}, {%0,%1,%2,%3}, %12, 0x0;"
                        : "+f"(acc[mt][j][0]), "+f"(acc[mt][j][1]),
                          "+f"(acc[mt][j][2]), "+f"(acc[mt][j][3])
                        : "r"(af[mt][0]), "r"(af[mt][1]), "r"(af[mt][2]), "r"(af[mt][3]),
                          "r"(bf[j][0]), "r"(bf[j][1]), "r"(bf[j][2]), "r"(bf[j][3]),
                          "r"(em[mt]));
                }
        }
    }
    CP_WAIT(0);

    #pragma unroll
    for (int mt = 0; mt < 4; mt++) {
        int r0 = tm * BM + wm * 64 + mt * 16 + (lid >> 2);
        #pragma unroll
        for (int nt = 0; nt < 8; nt++) {
            int c0 = tn * BN + wn * 64 + nt * 8 + (lid & 3) * 2;
            *(float2*)(out + (size_t)r0 * OUTDIM + c0) =
                make_float2(acc[mt][nt][0], acc[mt][nt][1]);
            *(float2*)(out + (size_t)(r0 + 8) * OUTDIM + c0) =
                make_float2(acc[mt][nt][2], acc[mt][nt][3]);
        }
    }
}

// ---------------------------------------------------------------------------
extern "C" void kernel_launch(void* const* d_in, const int* in_sizes, int n_in,
                              void* d_out, int out_size) {
    const float* x    = (const float*)d_in[0];
    const float* W    = (const float*)d_in[1];
    const float* bs   = (const float*)d_in[2];
    const float* grid = (const float*)d_in[3];
    float* out = (float*)d_out;

    cudaFuncSetAttribute(kan_gemm, cudaFuncAttributeMaxDynamicSharedMemorySize, SMEM_TOTAL);

    prep_B<<<dim3(KTOTC / 256, OUTDIM / 8), 256>>>(W, bs);
    prep_A<<<BATCH * 2, 256>>>(x, grid);
    kan_gemm<<<dim3(OUTDIM / BN, BATCH / BM), 256, SMEM_TOTAL>>>(out);
}